// round 15
// baseline (speedup 1.0000x reference)
#include <cuda_runtime.h>
#include <cuda_fp16.h>
#include <cstdint>

#define MAPSZ 67108864u
typedef unsigned uint;
typedef unsigned long long u64;

// ---------------- device scratch: single fp16 planes ----------------
__device__ __half g_q16[4194304];     // q * 0.125, [b][t][h][d]
__device__ __half g_k16[4194304];     // k,        [b][t][h][d]
__device__ __half g_pq16[8388608];    // phi_q,    [bh][t][128]
__device__ __half g_pk16[8388608];    // phi_k,    [bh][t][128]
__device__ float  g_sk[64 * 128];     // column sums of phi_k per bh

// ---------------- helpers ----------------
__device__ __forceinline__ float frcp(float x) { float r; asm("rcp.approx.ftz.f32 %0,%1;" : "=f"(r) : "f"(x)); return r; }
__device__ __forceinline__ uint packh(float hi, float lo) { uint r; asm("cvt.rn.f16x2.f32 %0,%1,%2;" : "=r"(r) : "f"(hi), "f"(lo)); return r; }
__device__ __forceinline__ float2 unpackh(uint w) { __half2 h = *(__half2*)&w; return __half22float2(h); }
__device__ __forceinline__ uint smem_u32(const void* p) {
    uint a; asm("{ .reg .u64 t; cvta.to.shared.u64 t,%1; cvt.u32.u64 %0,t; }" : "=r"(a) : "l"(p)); return a;
}
__device__ __forceinline__ void cp16(uint dst, const void* src) {
    asm volatile("cp.async.cg.shared.global [%0],[%1],16;" :: "r"(dst), "l"(src));
}
#define CP_COMMIT() asm volatile("cp.async.commit_group;")
#define CP_WAIT0()  asm volatile("cp.async.wait_group 0;")
#define CP_WAIT1()  asm volatile("cp.async.wait_group 1;")

__device__ __forceinline__ void ldsm4(uint* r, uint addr) {
    asm volatile("ldmatrix.sync.aligned.m8n8.x4.shared.b16 {%0,%1,%2,%3},[%4];"
                 : "=r"(r[0]), "=r"(r[1]), "=r"(r[2]), "=r"(r[3]) : "r"(addr));
}
__device__ __forceinline__ void mma168(float* c, const uint* a, uint b0, uint b1) {
    asm volatile("mma.sync.aligned.m16n8k16.row.col.f32.f16.f16.f32 "
                 "{%0,%1,%2,%3},{%4,%5,%6,%7},{%8,%9},{%0,%1,%2,%3};"
                 : "+f"(c[0]), "+f"(c[1]), "+f"(c[2]), "+f"(c[3])
                 : "r"(a[0]), "r"(a[1]), "r"(a[2]), "r"(a[3]), "r"(b0), "r"(b1));
}
__device__ __forceinline__ void stcs2(float* p, float a, float b) {
    asm volatile("st.global.cs.v2.f32 [%0],{%1,%2};" :: "l"(p), "f"(a), "f"(b) : "memory");
}
__device__ __forceinline__ void stcs4(float* p, float4 v) {
    asm volatile("st.global.cs.v4.f32 [%0],{%1,%2,%3,%4};"
                 :: "l"(p), "f"(v.x), "f"(v.y), "f"(v.z), "f"(v.w) : "memory");
}

// =====================================================================
// Kernel 1: feature maps via hi/lo fp16 mma. grid 1024; 256 threads.
// (R14-proven: uint4 staging, 8 lanes/row)
// =====================================================================
#define PXH 0u
#define PXL 18432u
#define PWH 36864u
#define PWL 46080u
#define PBIAS 55296u
#define PREP_SMEM 55552

__global__ __launch_bounds__(256) void hedgehog_prep3(
    const float* __restrict__ q, const float* __restrict__ k,
    const float* __restrict__ Wq, const float* __restrict__ bq,
    const float* __restrict__ Wk, const float* __restrict__ bk)
{
    extern __shared__ __align__(16) char sm[];
    const uint sb = smem_u32(sm);
    const int tid = threadIdx.x, bid = blockIdx.x;
    const int w = tid >> 5, l = tid & 31;
    const int tensor = bid >> 9, rem = bid & 511;
    const int b = rem >> 7, h = (rem >> 3) & 15, t0 = (rem & 7) * 128;
    const float* W  = tensor ? Wk : Wq;
    const float* bi = tensor ? bk : bq;
    const float* x  = tensor ? k  : q;
    const float sc  = tensor ? 1.0f : 0.125f;
    __half* xout = tensor ? g_k16 : g_q16;
    __half* pout = tensor ? g_pk16 : g_pq16;

    #pragma unroll
    for (int i = 0; i < 8; ++i) {
        int idx = i * 512 + tid * 2;
        int e = idx >> 6, d = idx & 63;
        float v0 = W[idx], v1 = W[idx + 1];
        uint hw = packh(v1, v0);
        float2 hf = unpackh(hw);
        *(uint*)(sm + PWH + (e * 72 + d) * 2) = hw;
        *(uint*)(sm + PWL + (e * 72 + d) * 2) = packh(v1 - hf.y, v0 - hf.x);
    }
    if (tid < 64) ((float*)(sm + PBIAS))[tid] = bi[tid];

    {
        const int j = tid & 7;
        const int rb = tid >> 3;
        #pragma unroll
        for (int p = 0; p < 4; ++p) {
            const int r = p * 32 + rb;
            const size_t xi = ((size_t)((b * 1024 + t0 + r) * 16 + h)) * 64 + j * 8;
            const float4* xp = (const float4*)(x + xi);
            float4 v0 = xp[0], v1 = xp[1];
            uint4 hh, ll, qv;
            hh.x = packh(v0.y, v0.x); hh.y = packh(v0.w, v0.z);
            hh.z = packh(v1.y, v1.x); hh.w = packh(v1.w, v1.z);
            float2 f0 = unpackh(hh.x), f1 = unpackh(hh.y), f2 = unpackh(hh.z), f3 = unpackh(hh.w);
            ll.x = packh(v0.y - f0.y, v0.x - f0.x); ll.y = packh(v0.w - f1.y, v0.z - f1.x);
            ll.z = packh(v1.y - f2.y, v1.x - f2.x); ll.w = packh(v1.w - f3.y, v1.z - f3.x);
            qv.x = packh(v0.y * sc, v0.x * sc); qv.y = packh(v0.w * sc, v0.z * sc);
            qv.z = packh(v1.y * sc, v1.x * sc); qv.w = packh(v1.w * sc, v1.z * sc);
            *(uint4*)(xout + xi) = qv;
            *(uint4*)(sm + PXH + r * 144u + j * 16u) = hh;
            *(uint4*)(sm + PXL + r * 144u + j * 16u) = ll;
        }
    }
    __syncthreads();

    const uint aK  = (uint)(l >> 4) * 16;
    const uint aH  = sb + PXH + (w * 16 + (l & 15)) * 144u + aK;
    const uint aL  = sb + PXL + (w * 16 + (l & 15)) * 144u + aK;
    const uint bRow = (uint)((l & 7) + ((l >> 3) & 1) * 8);

    float acc[8][4];
    #pragma unroll
    for (int nj = 0; nj < 8; ++nj)
        #pragma unroll
        for (int e = 0; e < 4; ++e) acc[nj][e] = 0.f;

    #pragma unroll
    for (int ks = 0; ks < 4; ++ks) {
        uint AH[4], AL[4];
        ldsm4(AH, aH + ks * 32);
        ldsm4(AL, aL + ks * 32);
        #pragma unroll
        for (int g = 0; g < 4; ++g) {
            uint BH[4], BL[4];
            const uint bo = (g * 16 + bRow) * 144u + aK + ks * 32;
            ldsm4(BH, sb + PWH + bo);
            ldsm4(BL, sb + PWL + bo);
            mma168(acc[g * 2],     AH, BH[0], BH[2]);
            mma168(acc[g * 2],     AL, BH[0], BH[2]);
            mma168(acc[g * 2],     AH, BL[0], BL[2]);
            mma168(acc[g * 2 + 1], AH, BH[1], BH[3]);
            mma168(acc[g * 2 + 1], AL, BH[1], BH[3]);
            mma168(acc[g * 2 + 1], AH, BL[1], BL[3]);
        }
    }

    const float* bb = (const float*)(sm + PBIAS);
    const int r0 = w * 16 + (l >> 2), r1 = r0 + 8;
    uint* p0 = (uint*)(pout + ((size_t)(b * 16 + h) * 1024 + t0 + r0) * 128);
    uint* p1 = (uint*)(pout + ((size_t)(b * 16 + h) * 1024 + t0 + r1) * 128);
    #pragma unroll
    for (int nj = 0; nj < 8; ++nj) {
        const int c = nj * 8 + (l & 3) * 2;
        const float b0 = bb[c], b1 = bb[c + 1];
        float e0 = __expf(acc[nj][0] + b0), e1 = __expf(acc[nj][1] + b1);
        float e2 = __expf(acc[nj][2] + b0), e3 = __expf(acc[nj][3] + b1);
        const int ci = nj * 4 + (l & 3);
        p0[ci]      = packh(e1, e0);
        p0[32 + ci] = packh(frcp(e1), frcp(e0));
        p1[ci]      = packh(e3, e2);
        p1[32 + ci] = packh(frcp(e3), frcp(e2));
    }
}

// =====================================================================
// Kernel 1b: column sums of phi_k. grid 64, 256 threads (coalesced).
// =====================================================================
__global__ __launch_bounds__(256) void hedgehog_ksum() {
    __shared__ float red[4][128];
    const int bh = blockIdx.x, tid = threadIdx.x;
    const int c2 = tid & 63, rg = tid >> 6;
    const __half2* src = (const __half2*)(g_pk16 + (size_t)bh * 131072) + c2;
    float sx = 0.f, sy = 0.f;
    #pragma unroll 8
    for (int t = rg; t < 1024; t += 4) {
        float2 v = __half22float2(src[(size_t)t * 64]);
        sx += v.x; sy += v.y;
    }
    red[rg][2 * c2] = sx; red[rg][2 * c2 + 1] = sy;
    __syncthreads();
    if (tid < 128)
        g_sk[bh * 128 + tid] = (red[0][tid] + red[1][tid]) + (red[2][tid] + red[3][tid]);
}

// =====================================================================
// Kernel 2a: map1 (softmax) — SINGLE sweep + L2-hot RMW normalize.
// grid (16,64), 256 threads, 3 CTAs/SM.
// Sweep: MMA + exp + store UNNORMALIZED (plain st -> L2-resident),
// rowsums in regs. Then RMW: read own 256KB (L2), scale, st.cs.
// =====================================================================
#define M1_Q   0u
#define M1_B0  9216u
#define M1_BSZ 9216u
#define M1_RS  27648u
#define M1_SMEM 27904

__device__ __forceinline__ void stageK(uint sb, uint bufo, int b, int h, int kr, int tid) {
    #pragma unroll
    for (int i = 0; i < 2; ++i) {
        int idx = i * 256 + tid;
        int r = idx >> 3, c = idx & 7;
        cp16(sb + bufo + r * 144u + c * 16u,
             g_k16 + ((size_t)((b * 1024 + kr + r) * 16 + h)) * 64 + c * 8);
    }
}

__global__ __launch_bounds__(256, 3) void hedgehog_map1(float* __restrict__ out)
{
    extern __shared__ __align__(16) char sm[];
    const uint sb = smem_u32(sm);
    const int tid = threadIdx.x, w = tid >> 5, l = tid & 31;
    const int wr = w >> 2, wc = w & 3;
    const int qt = blockIdx.x, bh = blockIdx.y;
    const int b = bh >> 4, h = bh & 15, t0 = qt * 64;
    float* rsf = (float*)(sm + M1_RS);

    #pragma unroll
    for (int i = 0; i < 2; ++i) {
        int idx = i * 256 + tid;
        int r = idx >> 3, c = idx & 7;
        cp16(sb + M1_Q + r * 144u + c * 16u,
             g_q16 + ((size_t)((b * 1024 + t0 + r) * 16 + h)) * 64 + c * 8);
    }
    stageK(sb, M1_B0, b, h, 0, tid);
    CP_COMMIT();
    if (tid < 64) rsf[tid] = 0.f;
    CP_WAIT0();
    __syncthreads();

    const uint aK = (uint)(l >> 4) * 16;
    const uint qA = sb + M1_Q + (wr * 32 + (l & 15)) * 144u + aK;
    const uint bRow = (uint)((l & 7) + ((l >> 3) & 1) * 8);
    const uint kBrel = (wc * 16 + bRow) * 144u + aK;

    uint QA0[4][4], QA1[4][4];
    #pragma unroll
    for (int ks = 0; ks < 4; ++ks) {
        ldsm4(QA0[ks], qA + ks * 32);
        ldsm4(QA1[ks], qA + 2304 + ks * 32);
    }

    float* o1 = out + ((size_t)((b * 1024 + t0 + wr * 32 + (l >> 2)) * 16 + h)) * 1024
                + wc * 16 + 2 * (l & 3);
    float rlo[2] = {0.f, 0.f}, rhi[2] = {0.f, 0.f};

    // ---- single sweep: compute + unnormalized store (plain, L2-resident) ----
    for (int kt = 0; kt < 16; ++kt) {
        if (kt < 15) { stageK(sb, M1_B0 + ((kt + 1) & 1) * M1_BSZ, b, h, (kt + 1) * 64, tid); CP_COMMIT(); CP_WAIT1(); }
        else CP_WAIT0();
        __syncthreads();
        const uint bufo = M1_B0 + (kt & 1) * M1_BSZ;

        float a1[2][2][4];
        #pragma unroll
        for (int mi = 0; mi < 2; ++mi)
            #pragma unroll
            for (int nj = 0; nj < 2; ++nj)
                #pragma unroll
                for (int e = 0; e < 4; ++e) a1[mi][nj][e] = 0.f;
        #pragma unroll
        for (int ks = 0; ks < 4; ++ks) {
            uint B[4];
            ldsm4(B, sb + bufo + kBrel + ks * 32);
            mma168(a1[0][0], QA0[ks], B[0], B[2]); mma168(a1[0][1], QA0[ks], B[1], B[3]);
            mma168(a1[1][0], QA1[ks], B[0], B[2]); mma168(a1[1][1], QA1[ks], B[1], B[3]);
        }
        #pragma unroll
        for (int mi = 0; mi < 2; ++mi)
            #pragma unroll
            for (int nj = 0; nj < 2; ++nj) {
                float e0 = __expf(a1[mi][nj][0]), e1 = __expf(a1[mi][nj][1]);
                float e2 = __expf(a1[mi][nj][2]), e3 = __expf(a1[mi][nj][3]);
                rlo[mi] += e0 + e1;
                rhi[mi] += e2 + e3;
                float* p = o1 + (size_t)mi * 262144 + kt * 64 + nj * 8;
                *(float2*)p               = make_float2(e0, e1);
                *(float2*)(p + 8 * 16384) = make_float2(e2, e3);
            }
        __syncthreads();
    }

    // ---- rowsum reduce -> rsf -> invert ----
    #pragma unroll
    for (int mi = 0; mi < 2; ++mi) {
        rlo[mi] += __shfl_xor_sync(0xffffffffu, rlo[mi], 1);
        rlo[mi] += __shfl_xor_sync(0xffffffffu, rlo[mi], 2);
        rhi[mi] += __shfl_xor_sync(0xffffffffu, rhi[mi], 1);
        rhi[mi] += __shfl_xor_sync(0xffffffffu, rhi[mi], 2);
        if ((l & 3) == 0) {
            atomicAdd(&rsf[wr * 32 + mi * 16 + (l >> 2)], rlo[mi]);
            atomicAdd(&rsf[wr * 32 + mi * 16 + (l >> 2) + 8], rhi[mi]);
        }
    }
    __syncthreads();
    if (tid < 64) rsf[tid] = 1.0f / rsf[tid];
    __syncthreads();

    // ---- RMW normalize (CTA's own 256KB, L2-hot) ----
    float4* pb = (float4*)(out + ((size_t)((b * 1024 + t0) * 16 + h)) * 1024);
    #pragma unroll 4
    for (int idx = tid; idx < 16384; idx += 256) {
        const int r = idx >> 8, c = idx & 255;
        float4 v = pb[(size_t)r * 4096 + c];
        const float s = rsf[r];
        v.x *= s; v.y *= s; v.z *= s; v.w *= s;
        stcs4((float*)(pb + (size_t)r * 4096 + c), v);
    }
}

// =====================================================================
// Kernel 2b: map2 with hoisted kt-invariant A fragments (R13-proven).
// =====================================================================
#define M2_PQ  0u
#define M2_B0  17408u
#define M2_BSZ 17408u
#define M2_SK  52224u
#define M2_IV  52736u
#define M2_SMEM 52992

__device__ __forceinline__ void stagePK(uint sb, uint bufo, int bh, int kr, int tid) {
    #pragma unroll
    for (int i = 0; i < 4; ++i) {
        int idx = i * 256 + tid;
        int r = idx >> 4, c = idx & 15;
        cp16(sb + bufo + r * 272u + c * 16u,
             g_pk16 + ((size_t)bh * 1024 + kr + r) * 128 + c * 8);
    }
}

__global__ __launch_bounds__(256, 2) void hedgehog_map2(float* __restrict__ out)
{
    extern __shared__ __align__(16) char sm[];
    const uint sb = smem_u32(sm);
    const int tid = threadIdx.x, w = tid >> 5, l = tid & 31;
    const int wr = w >> 2, wc = w & 3;
    const int qt = blockIdx.x, bh = blockIdx.y;
    const int b = bh >> 4, h = bh & 15, t0 = qt * 64;
    float* skf = (float*)(sm + M2_SK);
    float* ivf = (float*)(sm + M2_IV);

    #pragma unroll
    for (int i = 0; i < 4; ++i) {
        int idx = i * 256 + tid;
        int r = idx >> 4, c = idx & 15;
        cp16(sb + M2_PQ + r * 272u + c * 16u,
             g_pq16 + ((size_t)bh * 1024 + t0 + r) * 128 + c * 8);
    }
    stagePK(sb, M2_B0, bh, 0, tid);
    CP_COMMIT();
    if (tid < 128) skf[tid] = g_sk[bh * 128 + tid];
    CP_WAIT0();
    __syncthreads();

    if (tid < 64) {
        const uint* pr = (const uint*)(sm + M2_PQ + tid * 272);
        float s = 0.f;
        #pragma unroll 16
        for (int i = 0; i < 64; ++i) {
            float2 v = __half22float2(*(const __half2*)(pr + i));
            s = fmaf(v.x, skf[2 * i], s);
            s = fmaf(v.y, skf[2 * i + 1], s);
        }
        ivf[tid] = 1.0f / s;
    }
    __syncthreads();

    const uint aK = (uint)(l >> 4) * 16;
    const uint pA = sb + M2_PQ + (wr * 32 + (l & 15)) * 272u + aK;
    const uint bRow = (uint)((l & 7) + ((l >> 3) & 1) * 8);
    const uint pBrel = (wc * 16 + bRow) * 272u + aK;

    uint PA0[8][4], PA1[8][4];
    #pragma unroll
    for (int ks = 0; ks < 8; ++ks) {
        ldsm4(PA0[ks], pA + ks * 32);
        ldsm4(PA1[ks], pA + 4352 + ks * 32);
    }

    float* o2 = out + MAPSZ + ((size_t)((b * 1024 + t0 + wr * 32 + (l >> 2)) * 16 + h)) * 1024
                + wc * 16 + 2 * (l & 3);
    float iv0[2], iv1[2];
    #pragma unroll
    for (int mi = 0; mi < 2; ++mi) {
        iv0[mi] = ivf[wr * 32 + mi * 16 + (l >> 2)];
        iv1[mi] = ivf[wr * 32 + mi * 16 + (l >> 2) + 8];
    }

    for (int kt = 0; kt < 16; ++kt) {
        if (kt < 15) { stagePK(sb, M2_B0 + ((kt + 1) & 1) * M2_BSZ, bh, (kt + 1) * 64, tid); CP_COMMIT(); CP_WAIT1(); }
        else CP_WAIT0();
        __syncthreads();
        const uint bufo = M2_B0 + (kt & 1) * M2_BSZ;

        float a2[2][2][4];
        #pragma unroll
        for (int mi = 0; mi < 2; ++mi)
            #pragma unroll
            for (int nj = 0; nj < 2; ++nj)
                #pragma unroll
                for (int e = 0; e < 4; ++e) a2[mi][nj][e] = 0.f;
        #pragma unroll
        for (int ks = 0; ks < 8; ++ks) {
            uint B[4];
            ldsm4(B, sb + bufo + pBrel + ks * 32);
            mma168(a2[0][0], PA0[ks], B[0], B[2]); mma168(a2[0][1], PA0[ks], B[1], B[3]);
            mma168(a2[1][0], PA1[ks], B[0], B[2]); mma168(a2[1][1], PA1[ks], B[1], B[3]);
        }
        #pragma unroll
        for (int mi = 0; mi < 2; ++mi)
            #pragma unroll
            for (int nj = 0; nj < 2; ++nj) {
                float* p = o2 + (size_t)mi * 262144 + kt * 64 + nj * 8;
                stcs2(p,             a2[mi][nj][0] * iv0[mi], a2[mi][nj][1] * iv0[mi]);
                stcs2(p + 8 * 16384, a2[mi][nj][2] * iv1[mi], a2[mi][nj][3] * iv1[mi]);
            }
        __syncthreads();
    }
}

// =====================================================================
extern "C" void kernel_launch(void* const* d_in, const int* in_sizes, int n_in,
                              void* d_out, int out_size) {
    const float* q  = (const float*)d_in[0];
    const float* k  = (const float*)d_in[1];
    const float* Wq = (const float*)d_in[2];
    const float* bq = (const float*)d_in[3];
    const float* Wk = (const float*)d_in[4];
    const float* bk = (const float*)d_in[5];
    float* out = (float*)d_out;

    cudaFuncSetAttribute(hedgehog_prep3, cudaFuncAttributeMaxDynamicSharedMemorySize, PREP_SMEM);
    cudaFuncSetAttribute(hedgehog_map1, cudaFuncAttributeMaxDynamicSharedMemorySize, M1_SMEM);
    cudaFuncSetAttribute(hedgehog_map2, cudaFuncAttributeMaxDynamicSharedMemorySize, M2_SMEM);
    hedgehog_prep3<<<1024, 256, PREP_SMEM>>>(q, k, Wq, bq, Wk, bk);
    hedgehog_ksum<<<64, 256>>>();
    hedgehog_map1<<<dim3(16, 64), 256, M1_SMEM>>>(out);
    hedgehog_map2<<<dim3(16, 64), 256, M2_SMEM>>>(out);
}

// round 16
// speedup vs baseline: 1.2784x; 1.2784x over previous
#include <cuda_runtime.h>
#include <cuda_fp16.h>
#include <cstdint>

#define MAPSZ 67108864u
typedef unsigned uint;
typedef unsigned long long u64;

// ---------------- device scratch: single fp16 planes ----------------
__device__ __half g_q16[4194304];     // q * 0.125, [b][t][h][d]
__device__ __half g_k16[4194304];     // k,        [b][t][h][d]
__device__ __half g_pq16[8388608];    // phi_q,    [bh][t][128]
__device__ __half g_pk16[8388608];    // phi_k,    [bh][t][128]
__device__ float  g_sk[64 * 128];     // column sums of phi_k per bh

// ---------------- helpers ----------------
__device__ __forceinline__ float frcp(float x) { float r; asm("rcp.approx.ftz.f32 %0,%1;" : "=f"(r) : "f"(x)); return r; }
__device__ __forceinline__ uint packh(float hi, float lo) { uint r; asm("cvt.rn.f16x2.f32 %0,%1,%2;" : "=r"(r) : "f"(hi), "f"(lo)); return r; }
__device__ __forceinline__ float2 unpackh(uint w) { __half2 h = *(__half2*)&w; return __half22float2(h); }
__device__ __forceinline__ uint smem_u32(const void* p) {
    uint a; asm("{ .reg .u64 t; cvta.to.shared.u64 t,%1; cvt.u32.u64 %0,t; }" : "=r"(a) : "l"(p)); return a;
}
__device__ __forceinline__ void cp16(uint dst, const void* src) {
    asm volatile("cp.async.cg.shared.global [%0],[%1],16;" :: "r"(dst), "l"(src));
}
#define CP_COMMIT() asm volatile("cp.async.commit_group;")
#define CP_WAIT0()  asm volatile("cp.async.wait_group 0;")
#define CP_WAIT1()  asm volatile("cp.async.wait_group 1;")

__device__ __forceinline__ void ldsm4(uint* r, uint addr) {
    asm volatile("ldmatrix.sync.aligned.m8n8.x4.shared.b16 {%0,%1,%2,%3},[%4];"
                 : "=r"(r[0]), "=r"(r[1]), "=r"(r[2]), "=r"(r[3]) : "r"(addr));
}
__device__ __forceinline__ void mma168(float* c, const uint* a, uint b0, uint b1) {
    asm volatile("mma.sync.aligned.m16n8k16.row.col.f32.f16.f16.f32 "
                 "{%0,%1,%2,%3},{%4,%5,%6,%7},{%8,%9},{%0,%1,%2,%3};"
                 : "+f"(c[0]), "+f"(c[1]), "+f"(c[2]), "+f"(c[3])
                 : "r"(a[0]), "r"(a[1]), "r"(a[2]), "r"(a[3]), "r"(b0), "r"(b1));
}
__device__ __forceinline__ void stcs2(float* p, float a, float b) {
    asm volatile("st.global.cs.v2.f32 [%0],{%1,%2};" :: "l"(p), "f"(a), "f"(b) : "memory");
}

// =====================================================================
// Kernel 1: feature maps via hi/lo fp16 mma. grid 1024; 256 threads.
// (R14-proven: uint4 staging, 8 lanes/row)
// =====================================================================
#define PXH 0u
#define PXL 18432u
#define PWH 36864u
#define PWL 46080u
#define PBIAS 55296u
#define PREP_SMEM 55552

__global__ __launch_bounds__(256) void hedgehog_prep3(
    const float* __restrict__ q, const float* __restrict__ k,
    const float* __restrict__ Wq, const float* __restrict__ bq,
    const float* __restrict__ Wk, const float* __restrict__ bk)
{
    extern __shared__ __align__(16) char sm[];
    const uint sb = smem_u32(sm);
    const int tid = threadIdx.x, bid = blockIdx.x;
    const int w = tid >> 5, l = tid & 31;
    const int tensor = bid >> 9, rem = bid & 511;
    const int b = rem >> 7, h = (rem >> 3) & 15, t0 = (rem & 7) * 128;
    const float* W  = tensor ? Wk : Wq;
    const float* bi = tensor ? bk : bq;
    const float* x  = tensor ? k  : q;
    const float sc  = tensor ? 1.0f : 0.125f;
    __half* xout = tensor ? g_k16 : g_q16;
    __half* pout = tensor ? g_pk16 : g_pq16;

    #pragma unroll
    for (int i = 0; i < 8; ++i) {
        int idx = i * 512 + tid * 2;
        int e = idx >> 6, d = idx & 63;
        float v0 = W[idx], v1 = W[idx + 1];
        uint hw = packh(v1, v0);
        float2 hf = unpackh(hw);
        *(uint*)(sm + PWH + (e * 72 + d) * 2) = hw;
        *(uint*)(sm + PWL + (e * 72 + d) * 2) = packh(v1 - hf.y, v0 - hf.x);
    }
    if (tid < 64) ((float*)(sm + PBIAS))[tid] = bi[tid];

    {
        const int j = tid & 7;
        const int rb = tid >> 3;
        #pragma unroll
        for (int p = 0; p < 4; ++p) {
            const int r = p * 32 + rb;
            const size_t xi = ((size_t)((b * 1024 + t0 + r) * 16 + h)) * 64 + j * 8;
            const float4* xp = (const float4*)(x + xi);
            float4 v0 = xp[0], v1 = xp[1];
            uint4 hh, ll, qv;
            hh.x = packh(v0.y, v0.x); hh.y = packh(v0.w, v0.z);
            hh.z = packh(v1.y, v1.x); hh.w = packh(v1.w, v1.z);
            float2 f0 = unpackh(hh.x), f1 = unpackh(hh.y), f2 = unpackh(hh.z), f3 = unpackh(hh.w);
            ll.x = packh(v0.y - f0.y, v0.x - f0.x); ll.y = packh(v0.w - f1.y, v0.z - f1.x);
            ll.z = packh(v1.y - f2.y, v1.x - f2.x); ll.w = packh(v1.w - f3.y, v1.z - f3.x);
            qv.x = packh(v0.y * sc, v0.x * sc); qv.y = packh(v0.w * sc, v0.z * sc);
            qv.z = packh(v1.y * sc, v1.x * sc); qv.w = packh(v1.w * sc, v1.z * sc);
            *(uint4*)(xout + xi) = qv;
            *(uint4*)(sm + PXH + r * 144u + j * 16u) = hh;
            *(uint4*)(sm + PXL + r * 144u + j * 16u) = ll;
        }
    }
    __syncthreads();

    const uint aK  = (uint)(l >> 4) * 16;
    const uint aH  = sb + PXH + (w * 16 + (l & 15)) * 144u + aK;
    const uint aL  = sb + PXL + (w * 16 + (l & 15)) * 144u + aK;
    const uint bRow = (uint)((l & 7) + ((l >> 3) & 1) * 8);

    float acc[8][4];
    #pragma unroll
    for (int nj = 0; nj < 8; ++nj)
        #pragma unroll
        for (int e = 0; e < 4; ++e) acc[nj][e] = 0.f;

    #pragma unroll
    for (int ks = 0; ks < 4; ++ks) {
        uint AH[4], AL[4];
        ldsm4(AH, aH + ks * 32);
        ldsm4(AL, aL + ks * 32);
        #pragma unroll
        for (int g = 0; g < 4; ++g) {
            uint BH[4], BL[4];
            const uint bo = (g * 16 + bRow) * 144u + aK + ks * 32;
            ldsm4(BH, sb + PWH + bo);
            ldsm4(BL, sb + PWL + bo);
            mma168(acc[g * 2],     AH, BH[0], BH[2]);
            mma168(acc[g * 2],     AL, BH[0], BH[2]);
            mma168(acc[g * 2],     AH, BL[0], BL[2]);
            mma168(acc[g * 2 + 1], AH, BH[1], BH[3]);
            mma168(acc[g * 2 + 1], AL, BH[1], BH[3]);
            mma168(acc[g * 2 + 1], AH, BL[1], BL[3]);
        }
    }

    const float* bb = (const float*)(sm + PBIAS);
    const int r0 = w * 16 + (l >> 2), r1 = r0 + 8;
    uint* p0 = (uint*)(pout + ((size_t)(b * 16 + h) * 1024 + t0 + r0) * 128);
    uint* p1 = (uint*)(pout + ((size_t)(b * 16 + h) * 1024 + t0 + r1) * 128);
    #pragma unroll
    for (int nj = 0; nj < 8; ++nj) {
        const int c = nj * 8 + (l & 3) * 2;
        const float b0 = bb[c], b1 = bb[c + 1];
        float e0 = __expf(acc[nj][0] + b0), e1 = __expf(acc[nj][1] + b1);
        float e2 = __expf(acc[nj][2] + b0), e3 = __expf(acc[nj][3] + b1);
        const int ci = nj * 4 + (l & 3);
        p0[ci]      = packh(e1, e0);
        p0[32 + ci] = packh(frcp(e1), frcp(e0));
        p1[ci]      = packh(e3, e2);
        p1[32 + ci] = packh(frcp(e3), frcp(e2));
    }
}

// =====================================================================
// Kernel 1b: column sums of phi_k. grid 64, 256 threads (coalesced).
// =====================================================================
__global__ __launch_bounds__(256) void hedgehog_ksum() {
    __shared__ float red[4][128];
    const int bh = blockIdx.x, tid = threadIdx.x;
    const int c2 = tid & 63, rg = tid >> 6;
    const __half2* src = (const __half2*)(g_pk16 + (size_t)bh * 131072) + c2;
    float sx = 0.f, sy = 0.f;
    #pragma unroll 8
    for (int t = rg; t < 1024; t += 4) {
        float2 v = __half22float2(src[(size_t)t * 64]);
        sx += v.x; sy += v.y;
    }
    red[rg][2 * c2] = sx; red[rg][2 * c2 + 1] = sy;
    __syncthreads();
    if (tid < 128)
        g_sk[bh * 128 + tid] = (red[0][tid] + red[1][tid]) + (red[2][tid] + red[3][tid]);
}

// =====================================================================
// Kernel 2: MERGED maps, CTA-interleaved (which = blockIdx.x & 1).
// map1 body = R14-proven two-sweep. map2 body = R13-proven hoisted-PA.
// grid (32, 64), 256 threads, __launch_bounds__(256, 2), smem 54272.
// smem: map1: Q@0 (9216) | K bufs @9216 (2x9216)
//       map2: PQ@0 (17408) | PK bufs @17408 (2x17408)
//       tail: SK@52224, IV@52736, RS@54016
// =====================================================================
#define MM_B1   9216u
#define MM_BSZ1 9216u
#define MM_B2   17408u
#define MM_BSZ2 17408u
#define MM_SK   52224u
#define MM_IV   52736u
#define MM_RS   54016u
#define MM_SMEM 54272

__device__ __forceinline__ void stageK(uint sb, uint bufo, int b, int h, int kr, int tid) {
    #pragma unroll
    for (int i = 0; i < 2; ++i) {
        int idx = i * 256 + tid;
        int r = idx >> 3, c = idx & 7;
        cp16(sb + bufo + r * 144u + c * 16u,
             g_k16 + ((size_t)((b * 1024 + kr + r) * 16 + h)) * 64 + c * 8);
    }
}
__device__ __forceinline__ void stagePK(uint sb, uint bufo, int bh, int kr, int tid) {
    #pragma unroll
    for (int i = 0; i < 4; ++i) {
        int idx = i * 256 + tid;
        int r = idx >> 4, c = idx & 15;
        cp16(sb + bufo + r * 272u + c * 16u,
             g_pk16 + ((size_t)bh * 1024 + kr + r) * 128 + c * 8);
    }
}

__device__ void map1_body(char* sm, uint sb, float* out, int b, int h, int t0) {
    const int tid = threadIdx.x, w = tid >> 5, l = tid & 31;
    const int wr = w >> 2, wc = w & 3;
    float* rsf = (float*)(sm + MM_RS);

    #pragma unroll
    for (int i = 0; i < 2; ++i) {
        int idx = i * 256 + tid;
        int r = idx >> 3, c = idx & 7;
        cp16(sb + r * 144u + c * 16u,
             g_q16 + ((size_t)((b * 1024 + t0 + r) * 16 + h)) * 64 + c * 8);
    }
    stageK(sb, MM_B1, b, h, 0, tid);
    CP_COMMIT();
    if (tid < 64) rsf[tid] = 0.f;
    CP_WAIT0();
    __syncthreads();

    const uint aK = (uint)(l >> 4) * 16;
    const uint qA = sb + (wr * 32 + (l & 15)) * 144u + aK;
    const uint bRow = (uint)((l & 7) + ((l >> 3) & 1) * 8);
    const uint kBrel = (wc * 16 + bRow) * 144u + aK;

    uint QA0[4][4], QA1[4][4];
    #pragma unroll
    for (int ks = 0; ks < 4; ++ks) {
        ldsm4(QA0[ks], qA + ks * 32);
        ldsm4(QA1[ks], qA + 2304 + ks * 32);
    }

    float* o1 = out + ((size_t)((b * 1024 + t0 + wr * 32 + (l >> 2)) * 16 + h)) * 1024
                + wc * 16 + 2 * (l & 3);
    float rlo[2] = {0.f, 0.f}, rhi[2] = {0.f, 0.f};

    // sweep 1: rowsums only
    for (int kt = 0; kt < 16; ++kt) {
        if (kt < 15) { stageK(sb, MM_B1 + ((kt + 1) & 1) * MM_BSZ1, b, h, (kt + 1) * 64, tid); CP_COMMIT(); CP_WAIT1(); }
        else CP_WAIT0();
        __syncthreads();
        const uint bufo = MM_B1 + (kt & 1) * MM_BSZ1;

        float a1[2][2][4];
        #pragma unroll
        for (int mi = 0; mi < 2; ++mi)
            #pragma unroll
            for (int nj = 0; nj < 2; ++nj)
                #pragma unroll
                for (int e = 0; e < 4; ++e) a1[mi][nj][e] = 0.f;
        #pragma unroll
        for (int ks = 0; ks < 4; ++ks) {
            uint B[4];
            ldsm4(B, sb + bufo + kBrel + ks * 32);
            mma168(a1[0][0], QA0[ks], B[0], B[2]); mma168(a1[0][1], QA0[ks], B[1], B[3]);
            mma168(a1[1][0], QA1[ks], B[0], B[2]); mma168(a1[1][1], QA1[ks], B[1], B[3]);
        }
        #pragma unroll
        for (int mi = 0; mi < 2; ++mi)
            #pragma unroll
            for (int nj = 0; nj < 2; ++nj) {
                rlo[mi] += __expf(a1[mi][nj][0]) + __expf(a1[mi][nj][1]);
                rhi[mi] += __expf(a1[mi][nj][2]) + __expf(a1[mi][nj][3]);
            }
        __syncthreads();
    }

    #pragma unroll
    for (int mi = 0; mi < 2; ++mi) {
        rlo[mi] += __shfl_xor_sync(0xffffffffu, rlo[mi], 1);
        rlo[mi] += __shfl_xor_sync(0xffffffffu, rlo[mi], 2);
        rhi[mi] += __shfl_xor_sync(0xffffffffu, rhi[mi], 1);
        rhi[mi] += __shfl_xor_sync(0xffffffffu, rhi[mi], 2);
        if ((l & 3) == 0) {
            atomicAdd(&rsf[wr * 32 + mi * 16 + (l >> 2)], rlo[mi]);
            atomicAdd(&rsf[wr * 32 + mi * 16 + (l >> 2) + 8], rhi[mi]);
        }
    }
    __syncthreads();
    if (tid < 64) rsf[tid] = 1.0f / rsf[tid];
    __syncthreads();

    float rv0[2], rv1[2];
    #pragma unroll
    for (int mi = 0; mi < 2; ++mi) {
        rv0[mi] = rsf[wr * 32 + mi * 16 + (l >> 2)];
        rv1[mi] = rsf[wr * 32 + mi * 16 + (l >> 2) + 8];
    }

    // sweep 2: recompute + normalized store
    stageK(sb, MM_B1, b, h, 0, tid);
    CP_COMMIT();
    for (int kt = 0; kt < 16; ++kt) {
        if (kt < 15) { stageK(sb, MM_B1 + ((kt + 1) & 1) * MM_BSZ1, b, h, (kt + 1) * 64, tid); CP_COMMIT(); CP_WAIT1(); }
        else CP_WAIT0();
        __syncthreads();
        const uint bufo = MM_B1 + (kt & 1) * MM_BSZ1;

        float a1[2][2][4];
        #pragma unroll
        for (int mi = 0; mi < 2; ++mi)
            #pragma unroll
            for (int nj = 0; nj < 2; ++nj)
                #pragma unroll
                for (int e = 0; e < 4; ++e) a1[mi][nj][e] = 0.f;
        #pragma unroll
        for (int ks = 0; ks < 4; ++ks) {
            uint B[4];
            ldsm4(B, sb + bufo + kBrel + ks * 32);
            mma168(a1[0][0], QA0[ks], B[0], B[2]); mma168(a1[0][1], QA0[ks], B[1], B[3]);
            mma168(a1[1][0], QA1[ks], B[0], B[2]); mma168(a1[1][1], QA1[ks], B[1], B[3]);
        }
        #pragma unroll
        for (int mi = 0; mi < 2; ++mi)
            #pragma unroll
            for (int nj = 0; nj < 2; ++nj) {
                float* p = o1 + (size_t)mi * 262144 + kt * 64 + nj * 8;
                stcs2(p,             __expf(a1[mi][nj][0]) * rv0[mi], __expf(a1[mi][nj][1]) * rv0[mi]);
                stcs2(p + 8 * 16384, __expf(a1[mi][nj][2]) * rv1[mi], __expf(a1[mi][nj][3]) * rv1[mi]);
            }
        __syncthreads();
    }
}

__device__ void map2_body(char* sm, uint sb, float* out, int b, int h, int bh, int t0) {
    const int tid = threadIdx.x, w = tid >> 5, l = tid & 31;
    const int wr = w >> 2, wc = w & 3;
    float* skf = (float*)(sm + MM_SK);
    float* ivf = (float*)(sm + MM_IV);

    #pragma unroll
    for (int i = 0; i < 4; ++i) {
        int idx = i * 256 + tid;
        int r = idx >> 4, c = idx & 15;
        cp16(sb + r * 272u + c * 16u,
             g_pq16 + ((size_t)bh * 1024 + t0 + r) * 128 + c * 8);
    }
    stagePK(sb, MM_B2, bh, 0, tid);
    CP_COMMIT();
    if (tid < 128) skf[tid] = g_sk[bh * 128 + tid];
    CP_WAIT0();
    __syncthreads();

    if (tid < 64) {
        const uint* pr = (const uint*)(sm + tid * 272);
        float s = 0.f;
        #pragma unroll 16
        for (int i = 0; i < 64; ++i) {
            float2 v = __half22float2(*(const __half2*)(pr + i));
            s = fmaf(v.x, skf[2 * i], s);
            s = fmaf(v.y, skf[2 * i + 1], s);
        }
        ivf[tid] = 1.0f / s;
    }
    __syncthreads();

    const uint aK = (uint)(l >> 4) * 16;
    const uint pA = sb + (wr * 32 + (l & 15)) * 272u + aK;
    const uint bRow = (uint)((l & 7) + ((l >> 3) & 1) * 8);
    const uint pBrel = (wc * 16 + bRow) * 272u + aK;

    uint PA0[8][4], PA1[8][4];
    #pragma unroll
    for (int ks = 0; ks < 8; ++ks) {
        ldsm4(PA0[ks], pA + ks * 32);
        ldsm4(PA1[ks], pA + 4352 + ks * 32);
    }

    float* o2 = out + MAPSZ + ((size_t)((b * 1024 + t0 + wr * 32 + (l >> 2)) * 16 + h)) * 1024
                + wc * 16 + 2 * (l & 3);
    float iv0[2], iv1[2];
    #pragma unroll
    for (int mi = 0; mi < 2; ++mi) {
        iv0[mi] = ivf[wr * 32 + mi * 16 + (l >> 2)];
        iv1[mi] = ivf[wr * 32 + mi * 16 + (l >> 2) + 8];
    }

    for (int kt = 0; kt < 16; ++kt) {
        if (kt < 15) { stagePK(sb, MM_B2 + ((kt + 1) & 1) * MM_BSZ2, bh, (kt + 1) * 64, tid); CP_COMMIT(); CP_WAIT1(); }
        else CP_WAIT0();
        __syncthreads();
        const uint bufo = MM_B2 + (kt & 1) * MM_BSZ2;

        float a2[2][2][4];
        #pragma unroll
        for (int mi = 0; mi < 2; ++mi)
            #pragma unroll
            for (int nj = 0; nj < 2; ++nj)
                #pragma unroll
                for (int e = 0; e < 4; ++e) a2[mi][nj][e] = 0.f;
        #pragma unroll
        for (int ks = 0; ks < 8; ++ks) {
            uint B[4];
            ldsm4(B, sb + bufo + pBrel + ks * 32);
            mma168(a2[0][0], PA0[ks], B[0], B[2]); mma168(a2[0][1], PA0[ks], B[1], B[3]);
            mma168(a2[1][0], PA1[ks], B[0], B[2]); mma168(a2[1][1], PA1[ks], B[1], B[3]);
        }
        #pragma unroll
        for (int mi = 0; mi < 2; ++mi)
            #pragma unroll
            for (int nj = 0; nj < 2; ++nj) {
                float* p = o2 + (size_t)mi * 262144 + kt * 64 + nj * 8;
                stcs2(p,             a2[mi][nj][0] * iv0[mi], a2[mi][nj][1] * iv0[mi]);
                stcs2(p + 8 * 16384, a2[mi][nj][2] * iv1[mi], a2[mi][nj][3] * iv1[mi]);
            }
        __syncthreads();
    }
}

__global__ __launch_bounds__(256, 2) void hedgehog_maps(float* __restrict__ out)
{
    extern __shared__ __align__(16) char sm[];
    const uint sb = smem_u32(sm);
    const int which = blockIdx.x & 1;
    const int qt = blockIdx.x >> 1;
    const int bh = blockIdx.y;
    const int b = bh >> 4, h = bh & 15, t0 = qt * 64;
    if (which == 0) map1_body(sm, sb, out, b, h, t0);
    else            map2_body(sm, sb, out, b, h, bh, t0);
}

// =====================================================================
extern "C" void kernel_launch(void* const* d_in, const int* in_sizes, int n_in,
                              void* d_out, int out_size) {
    const float* q  = (const float*)d_in[0];
    const float* k  = (const float*)d_in[1];
    const float* Wq = (const float*)d_in[2];
    const float* bq = (const float*)d_in[3];
    const float* Wk = (const float*)d_in[4];
    const float* bk = (const float*)d_in[5];
    float* out = (float*)d_out;

    cudaFuncSetAttribute(hedgehog_prep3, cudaFuncAttributeMaxDynamicSharedMemorySize, PREP_SMEM);
    cudaFuncSetAttribute(hedgehog_maps, cudaFuncAttributeMaxDynamicSharedMemorySize, MM_SMEM);
    hedgehog_prep3<<<1024, 256, PREP_SMEM>>>(q, k, Wq, bq, Wk, bk);
    hedgehog_ksum<<<64, 256>>>();
    hedgehog_maps<<<dim3(32, 64), 256, MM_SMEM>>>(out);
}

// round 17
// speedup vs baseline: 1.3483x; 1.0546x over previous
#include <cuda_runtime.h>
#include <cuda_fp16.h>
#include <cstdint>

#define MAPSZ 67108864u
typedef unsigned uint;
typedef unsigned long long u64;

// ---------------- device scratch: single fp16 planes ----------------
__device__ __half g_q16[4194304];
__device__ __half g_k16[4194304];
__device__ __half g_pq16[8388608];
__device__ __half g_pk16[8388608];
__device__ float  g_sk[64 * 128];

// ---------------- helpers ----------------
__device__ __forceinline__ float frcp(float x) { float r; asm("rcp.approx.ftz.f32 %0,%1;" : "=f"(r) : "f"(x)); return r; }
__device__ __forceinline__ uint packh(float hi, float lo) { uint r; asm("cvt.rn.f16x2.f32 %0,%1,%2;" : "=r"(r) : "f"(hi), "f"(lo)); return r; }
__device__ __forceinline__ float2 unpackh(uint w) { __half2 h = *(__half2*)&w; return __half22float2(h); }
__device__ __forceinline__ uint smem_u32(const void* p) {
    uint a; asm("{ .reg .u64 t; cvta.to.shared.u64 t,%1; cvt.u32.u64 %0,t; }" : "=r"(a) : "l"(p)); return a;
}
__device__ __forceinline__ void cp16(uint dst, const void* src) {
    asm volatile("cp.async.cg.shared.global [%0],[%1],16;" :: "r"(dst), "l"(src));
}
#define CP_COMMIT() asm volatile("cp.async.commit_group;")
#define CP_WAIT0()  asm volatile("cp.async.wait_group 0;")
#define CP_WAIT1()  asm volatile("cp.async.wait_group 1;")
#define CP_WAIT2()  asm volatile("cp.async.wait_group 2;")

__device__ __forceinline__ void ldsm4(uint* r, uint addr) {
    asm volatile("ldmatrix.sync.aligned.m8n8.x4.shared.b16 {%0,%1,%2,%3},[%4];"
                 : "=r"(r[0]), "=r"(r[1]), "=r"(r[2]), "=r"(r[3]) : "r"(addr));
}
__device__ __forceinline__ void mma168(float* c, const uint* a, uint b0, uint b1) {
    asm volatile("mma.sync.aligned.m16n8k16.row.col.f32.f16.f16.f32 "
                 "{%0,%1,%2,%3},{%4,%5,%6,%7},{%8,%9},{%0,%1,%2,%3};"
                 : "+f"(c[0]), "+f"(c[1]), "+f"(c[2]), "+f"(c[3])
                 : "r"(a[0]), "r"(a[1]), "r"(a[2]), "r"(a[3]), "r"(b0), "r"(b1));
}
__device__ __forceinline__ void stcs2(float* p, float a, float b) {
    asm volatile("st.global.cs.v2.f32 [%0],{%1,%2};" :: "l"(p), "f"(a), "f"(b) : "memory");
}

// =====================================================================
// Kernel 1: feature maps (R14-proven). grid 1024; 256 threads.
// =====================================================================
#define PXH 0u
#define PXL 18432u
#define PWH 36864u
#define PWL 46080u
#define PBIAS 55296u
#define PREP_SMEM 55552

__global__ __launch_bounds__(256) void hedgehog_prep3(
    const float* __restrict__ q, const float* __restrict__ k,
    const float* __restrict__ Wq, const float* __restrict__ bq,
    const float* __restrict__ Wk, const float* __restrict__ bk)
{
    extern __shared__ __align__(16) char sm[];
    const uint sb = smem_u32(sm);
    const int tid = threadIdx.x, bid = blockIdx.x;
    const int w = tid >> 5, l = tid & 31;
    const int tensor = bid >> 9, rem = bid & 511;
    const int b = rem >> 7, h = (rem >> 3) & 15, t0 = (rem & 7) * 128;
    const float* W  = tensor ? Wk : Wq;
    const float* bi = tensor ? bk : bq;
    const float* x  = tensor ? k  : q;
    const float sc  = tensor ? 1.0f : 0.125f;
    __half* xout = tensor ? g_k16 : g_q16;
    __half* pout = tensor ? g_pk16 : g_pq16;

    #pragma unroll
    for (int i = 0; i < 8; ++i) {
        int idx = i * 512 + tid * 2;
        int e = idx >> 6, d = idx & 63;
        float v0 = W[idx], v1 = W[idx + 1];
        uint hw = packh(v1, v0);
        float2 hf = unpackh(hw);
        *(uint*)(sm + PWH + (e * 72 + d) * 2) = hw;
        *(uint*)(sm + PWL + (e * 72 + d) * 2) = packh(v1 - hf.y, v0 - hf.x);
    }
    if (tid < 64) ((float*)(sm + PBIAS))[tid] = bi[tid];

    {
        const int j = tid & 7;
        const int rb = tid >> 3;
        #pragma unroll
        for (int p = 0; p < 4; ++p) {
            const int r = p * 32 + rb;
            const size_t xi = ((size_t)((b * 1024 + t0 + r) * 16 + h)) * 64 + j * 8;
            const float4* xp = (const float4*)(x + xi);
            float4 v0 = xp[0], v1 = xp[1];
            uint4 hh, ll, qv;
            hh.x = packh(v0.y, v0.x); hh.y = packh(v0.w, v0.z);
            hh.z = packh(v1.y, v1.x); hh.w = packh(v1.w, v1.z);
            float2 f0 = unpackh(hh.x), f1 = unpackh(hh.y), f2 = unpackh(hh.z), f3 = unpackh(hh.w);
            ll.x = packh(v0.y - f0.y, v0.x - f0.x); ll.y = packh(v0.w - f1.y, v0.z - f1.x);
            ll.z = packh(v1.y - f2.y, v1.x - f2.x); ll.w = packh(v1.w - f3.y, v1.z - f3.x);
            qv.x = packh(v0.y * sc, v0.x * sc); qv.y = packh(v0.w * sc, v0.z * sc);
            qv.z = packh(v1.y * sc, v1.x * sc); qv.w = packh(v1.w * sc, v1.z * sc);
            *(uint4*)(xout + xi) = qv;
            *(uint4*)(sm + PXH + r * 144u + j * 16u) = hh;
            *(uint4*)(sm + PXL + r * 144u + j * 16u) = ll;
        }
    }
    __syncthreads();

    const uint aK  = (uint)(l >> 4) * 16;
    const uint aH  = sb + PXH + (w * 16 + (l & 15)) * 144u + aK;
    const uint aL  = sb + PXL + (w * 16 + (l & 15)) * 144u + aK;
    const uint bRow = (uint)((l & 7) + ((l >> 3) & 1) * 8);

    float acc[8][4];
    #pragma unroll
    for (int nj = 0; nj < 8; ++nj)
        #pragma unroll
        for (int e = 0; e < 4; ++e) acc[nj][e] = 0.f;

    #pragma unroll
    for (int ks = 0; ks < 4; ++ks) {
        uint AH[4], AL[4];
        ldsm4(AH, aH + ks * 32);
        ldsm4(AL, aL + ks * 32);
        #pragma unroll
        for (int g = 0; g < 4; ++g) {
            uint BH[4], BL[4];
            const uint bo = (g * 16 + bRow) * 144u + aK + ks * 32;
            ldsm4(BH, sb + PWH + bo);
            ldsm4(BL, sb + PWL + bo);
            mma168(acc[g * 2],     AH, BH[0], BH[2]);
            mma168(acc[g * 2],     AL, BH[0], BH[2]);
            mma168(acc[g * 2],     AH, BL[0], BL[2]);
            mma168(acc[g * 2 + 1], AH, BH[1], BH[3]);
            mma168(acc[g * 2 + 1], AL, BH[1], BH[3]);
            mma168(acc[g * 2 + 1], AH, BL[1], BL[3]);
        }
    }

    const float* bb = (const float*)(sm + PBIAS);
    const int r0 = w * 16 + (l >> 2), r1 = r0 + 8;
    uint* p0 = (uint*)(pout + ((size_t)(b * 16 + h) * 1024 + t0 + r0) * 128);
    uint* p1 = (uint*)(pout + ((size_t)(b * 16 + h) * 1024 + t0 + r1) * 128);
    #pragma unroll
    for (int nj = 0; nj < 8; ++nj) {
        const int c = nj * 8 + (l & 3) * 2;
        const float b0 = bb[c], b1 = bb[c + 1];
        float e0 = __expf(acc[nj][0] + b0), e1 = __expf(acc[nj][1] + b1);
        float e2 = __expf(acc[nj][2] + b0), e3 = __expf(acc[nj][3] + b1);
        const int ci = nj * 4 + (l & 3);
        p0[ci]      = packh(e1, e0);
        p0[32 + ci] = packh(frcp(e1), frcp(e0));
        p1[ci]      = packh(e3, e2);
        p1[32 + ci] = packh(frcp(e3), frcp(e2));
    }
}

// =====================================================================
// Kernel 1b: column sums of phi_k. grid 64, 256 threads (coalesced).
// =====================================================================
__global__ __launch_bounds__(256) void hedgehog_ksum() {
    __shared__ float red[4][128];
    const int bh = blockIdx.x, tid = threadIdx.x;
    const int c2 = tid & 63, rg = tid >> 6;
    const __half2* src = (const __half2*)(g_pk16 + (size_t)bh * 131072) + c2;
    float sx = 0.f, sy = 0.f;
    #pragma unroll 8
    for (int t = rg; t < 1024; t += 4) {
        float2 v = __half22float2(src[(size_t)t * 64]);
        sx += v.x; sy += v.y;
    }
    red[rg][2 * c2] = sx; red[rg][2 * c2 + 1] = sy;
    __syncthreads();
    if (tid < 128)
        g_sk[bh * 128 + tid] = (red[0][tid] + red[1][tid]) + (red[2][tid] + red[3][tid]);
}

// =====================================================================
// Kernel 2a: map1 (softmax), two-sweep, QUAD-buffered K staging,
// single sync per kt. grid (16,64), 256 threads, 3 CTAs/SM. smem 46.3KB.
// =====================================================================
#define M1_Q   0u
#define M1_B0  9216u
#define M1_BSZ 9216u
#define M1_RS  46080u
#define M1_SMEM 46336

__device__ __forceinline__ void stageK(uint sb, uint bufo, int b, int h, int kr, int tid) {
    #pragma unroll
    for (int i = 0; i < 2; ++i) {
        int idx = i * 256 + tid;
        int r = idx >> 3, c = idx & 7;
        cp16(sb + bufo + r * 144u + c * 16u,
             g_k16 + ((size_t)((b * 1024 + kr + r) * 16 + h)) * 64 + c * 8);
    }
}

__global__ __launch_bounds__(256, 3) void hedgehog_map1(float* __restrict__ out)
{
    extern __shared__ __align__(16) char sm[];
    const uint sb = smem_u32(sm);
    const int tid = threadIdx.x, w = tid >> 5, l = tid & 31;
    const int wr = w >> 2, wc = w & 3;
    const int qt = blockIdx.x, bh = blockIdx.y;
    const int b = bh >> 4, h = bh & 15, t0 = qt * 64;
    float* rsf = (float*)(sm + M1_RS);

    #pragma unroll
    for (int i = 0; i < 2; ++i) {
        int idx = i * 256 + tid;
        int r = idx >> 3, c = idx & 7;
        cp16(sb + M1_Q + r * 144u + c * 16u,
             g_q16 + ((size_t)((b * 1024 + t0 + r) * 16 + h)) * 64 + c * 8);
    }
    stageK(sb, M1_B0, b, h, 0, tid);
    CP_COMMIT();
    stageK(sb, M1_B0 + M1_BSZ, b, h, 64, tid);
    CP_COMMIT();
    if (tid < 64) rsf[tid] = 0.f;
    CP_WAIT1();     // Q + buf0 ready
    __syncthreads();

    const uint aK = (uint)(l >> 4) * 16;
    const uint qA = sb + M1_Q + (wr * 32 + (l & 15)) * 144u + aK;
    const uint bRow = (uint)((l & 7) + ((l >> 3) & 1) * 8);
    const uint kBrel = (wc * 16 + bRow) * 144u + aK;

    uint QA0[4][4], QA1[4][4];
    #pragma unroll
    for (int ks = 0; ks < 4; ++ks) {
        ldsm4(QA0[ks], qA + ks * 32);
        ldsm4(QA1[ks], qA + 2304 + ks * 32);
    }

    float* o1 = out + ((size_t)((b * 1024 + t0 + wr * 32 + (l >> 2)) * 16 + h)) * 1024
                + wc * 16 + 2 * (l & 3);
    float rlo[2] = {0.f, 0.f}, rhi[2] = {0.f, 0.f};

    // ---- sweep 1: rowsums only ----
    for (int kt = 0; kt < 16; ++kt) {
        if (kt <= 13) { stageK(sb, M1_B0 + ((kt + 2) & 3) * M1_BSZ, b, h, (kt + 2) * 64, tid); CP_COMMIT(); CP_WAIT2(); }
        else if (kt == 14) CP_WAIT1();
        else CP_WAIT0();
        __syncthreads();
        const uint bufo = M1_B0 + (kt & 3) * M1_BSZ;

        float a1[2][2][4];
        #pragma unroll
        for (int mi = 0; mi < 2; ++mi)
            #pragma unroll
            for (int nj = 0; nj < 2; ++nj)
                #pragma unroll
                for (int e = 0; e < 4; ++e) a1[mi][nj][e] = 0.f;
        #pragma unroll
        for (int ks = 0; ks < 4; ++ks) {
            uint B[4];
            ldsm4(B, sb + bufo + kBrel + ks * 32);
            mma168(a1[0][0], QA0[ks], B[0], B[2]); mma168(a1[0][1], QA0[ks], B[1], B[3]);
            mma168(a1[1][0], QA1[ks], B[0], B[2]); mma168(a1[1][1], QA1[ks], B[1], B[3]);
        }
        #pragma unroll
        for (int mi = 0; mi < 2; ++mi)
            #pragma unroll
            for (int nj = 0; nj < 2; ++nj) {
                rlo[mi] += __expf(a1[mi][nj][0]) + __expf(a1[mi][nj][1]);
                rhi[mi] += __expf(a1[mi][nj][2]) + __expf(a1[mi][nj][3]);
            }
    }

    #pragma unroll
    for (int mi = 0; mi < 2; ++mi) {
        rlo[mi] += __shfl_xor_sync(0xffffffffu, rlo[mi], 1);
        rlo[mi] += __shfl_xor_sync(0xffffffffu, rlo[mi], 2);
        rhi[mi] += __shfl_xor_sync(0xffffffffu, rhi[mi], 1);
        rhi[mi] += __shfl_xor_sync(0xffffffffu, rhi[mi], 2);
        if ((l & 3) == 0) {
            atomicAdd(&rsf[wr * 32 + mi * 16 + (l >> 2)], rlo[mi]);
            atomicAdd(&rsf[wr * 32 + mi * 16 + (l >> 2) + 8], rhi[mi]);
        }
    }
    __syncthreads();
    if (tid < 64) rsf[tid] = 1.0f / rsf[tid];
    __syncthreads();

    float rv0[2], rv1[2];
    #pragma unroll
    for (int mi = 0; mi < 2; ++mi) {
        rv0[mi] = rsf[wr * 32 + mi * 16 + (l >> 2)];
        rv1[mi] = rsf[wr * 32 + mi * 16 + (l >> 2) + 8];
    }

    // ---- sweep 2: recompute + normalized store ----
    stageK(sb, M1_B0, b, h, 0, tid);
    CP_COMMIT();
    stageK(sb, M1_B0 + M1_BSZ, b, h, 64, tid);
    CP_COMMIT();
    for (int kt = 0; kt < 16; ++kt) {
        if (kt <= 13) { stageK(sb, M1_B0 + ((kt + 2) & 3) * M1_BSZ, b, h, (kt + 2) * 64, tid); CP_COMMIT(); CP_WAIT2(); }
        else if (kt == 14) CP_WAIT1();
        else CP_WAIT0();
        __syncthreads();
        const uint bufo = M1_B0 + (kt & 3) * M1_BSZ;

        float a1[2][2][4];
        #pragma unroll
        for (int mi = 0; mi < 2; ++mi)
            #pragma unroll
            for (int nj = 0; nj < 2; ++nj)
                #pragma unroll
                for (int e = 0; e < 4; ++e) a1[mi][nj][e] = 0.f;
        #pragma unroll
        for (int ks = 0; ks < 4; ++ks) {
            uint B[4];
            ldsm4(B, sb + bufo + kBrel + ks * 32);
            mma168(a1[0][0], QA0[ks], B[0], B[2]); mma168(a1[0][1], QA0[ks], B[1], B[3]);
            mma168(a1[1][0], QA1[ks], B[0], B[2]); mma168(a1[1][1], QA1[ks], B[1], B[3]);
        }
        #pragma unroll
        for (int mi = 0; mi < 2; ++mi)
            #pragma unroll
            for (int nj = 0; nj < 2; ++nj) {
                float* p = o1 + (size_t)mi * 262144 + kt * 64 + nj * 8;
                stcs2(p,             __expf(a1[mi][nj][0]) * rv0[mi], __expf(a1[mi][nj][1]) * rv0[mi]);
                stcs2(p + 8 * 16384, __expf(a1[mi][nj][2]) * rv1[mi], __expf(a1[mi][nj][3]) * rv1[mi]);
            }
    }
}

// =====================================================================
// Kernel 2b: map2, hoisted A-fragments, QUAD-buffered PK staging,
// single sync per kt. grid (16,64), 256 threads, 2 CTAs/SM. smem 87.8KB.
// =====================================================================
#define M2_PQ  0u
#define M2_B0  17408u
#define M2_BSZ 17408u
#define M2_SK  87040u
#define M2_IV  87552u
#define M2_SMEM 87808

__device__ __forceinline__ void stagePK(uint sb, uint bufo, int bh, int kr, int tid) {
    #pragma unroll
    for (int i = 0; i < 4; ++i) {
        int idx = i * 256 + tid;
        int r = idx >> 4, c = idx & 15;
        cp16(sb + bufo + r * 272u + c * 16u,
             g_pk16 + ((size_t)bh * 1024 + kr + r) * 128 + c * 8);
    }
}

__global__ __launch_bounds__(256, 2) void hedgehog_map2(float* __restrict__ out)
{
    extern __shared__ __align__(16) char sm[];
    const uint sb = smem_u32(sm);
    const int tid = threadIdx.x, w = tid >> 5, l = tid & 31;
    const int wr = w >> 2, wc = w & 3;
    const int qt = blockIdx.x, bh = blockIdx.y;
    const int b = bh >> 4, h = bh & 15, t0 = qt * 64;
    float* skf = (float*)(sm + M2_SK);
    float* ivf = (float*)(sm + M2_IV);

    #pragma unroll
    for (int i = 0; i < 4; ++i) {
        int idx = i * 256 + tid;
        int r = idx >> 4, c = idx & 15;
        cp16(sb + M2_PQ + r * 272u + c * 16u,
             g_pq16 + ((size_t)bh * 1024 + t0 + r) * 128 + c * 8);
    }
    stagePK(sb, M2_B0, bh, 0, tid);
    CP_COMMIT();
    stagePK(sb, M2_B0 + M2_BSZ, bh, 64, tid);
    CP_COMMIT();
    if (tid < 128) skf[tid] = g_sk[bh * 128 + tid];
    CP_WAIT1();     // PQ + buf0 ready
    __syncthreads();

    if (tid < 64) {
        const uint* pr = (const uint*)(sm + M2_PQ + tid * 272);
        float s = 0.f;
        #pragma unroll 16
        for (int i = 0; i < 64; ++i) {
            float2 v = __half22float2(*(const __half2*)(pr + i));
            s = fmaf(v.x, skf[2 * i], s);
            s = fmaf(v.y, skf[2 * i + 1], s);
        }
        ivf[tid] = 1.0f / s;
    }
    __syncthreads();

    const uint aK = (uint)(l >> 4) * 16;
    const uint pA = sb + M2_PQ + (wr * 32 + (l & 15)) * 272u + aK;
    const uint bRow = (uint)((l & 7) + ((l >> 3) & 1) * 8);
    const uint pBrel = (wc * 16 + bRow) * 272u + aK;

    uint PA0[8][4], PA1[8][4];
    #pragma unroll
    for (int ks = 0; ks < 8; ++ks) {
        ldsm4(PA0[ks], pA + ks * 32);
        ldsm4(PA1[ks], pA + 4352 + ks * 32);
    }

    float* o2 = out + MAPSZ + ((size_t)((b * 1024 + t0 + wr * 32 + (l >> 2)) * 16 + h)) * 1024
                + wc * 16 + 2 * (l & 3);
    float iv0[2], iv1[2];
    #pragma unroll
    for (int mi = 0; mi < 2; ++mi) {
        iv0[mi] = ivf[wr * 32 + mi * 16 + (l >> 2)];
        iv1[mi] = ivf[wr * 32 + mi * 16 + (l >> 2) + 8];
    }

    for (int kt = 0; kt < 16; ++kt) {
        if (kt <= 13) { stagePK(sb, M2_B0 + ((kt + 2) & 3) * M2_BSZ, bh, (kt + 2) * 64, tid); CP_COMMIT(); CP_WAIT2(); }
        else if (kt == 14) CP_WAIT1();
        else CP_WAIT0();
        __syncthreads();
        const uint bufo = M2_B0 + (kt & 3) * M2_BSZ;

        float a2[2][2][4];
        #pragma unroll
        for (int mi = 0; mi < 2; ++mi)
            #pragma unroll
            for (int nj = 0; nj < 2; ++nj)
                #pragma unroll
                for (int e = 0; e < 4; ++e) a2[mi][nj][e] = 0.f;
        #pragma unroll
        for (int ks = 0; ks < 8; ++ks) {
            uint B[4];
            ldsm4(B, sb + bufo + pBrel + ks * 32);
            mma168(a2[0][0], PA0[ks], B[0], B[2]); mma168(a2[0][1], PA0[ks], B[1], B[3]);
            mma168(a2[1][0], PA1[ks], B[0], B[2]); mma168(a2[1][1], PA1[ks], B[1], B[3]);
        }
        #pragma unroll
        for (int mi = 0; mi < 2; ++mi)
            #pragma unroll
            for (int nj = 0; nj < 2; ++nj) {
                float* p = o2 + (size_t)mi * 262144 + kt * 64 + nj * 8;
                stcs2(p,             a2[mi][nj][0] * iv0[mi], a2[mi][nj][1] * iv0[mi]);
                stcs2(p + 8 * 16384, a2[mi][nj][2] * iv1[mi], a2[mi][nj][3] * iv1[mi]);
            }
    }
}

// =====================================================================
extern "C" void kernel_launch(void* const* d_in, const int* in_sizes, int n_in,
                              void* d_out, int out_size) {
    const float* q  = (const float*)d_in[0];
    const float* k  = (const float*)d_in[1];
    const float* Wq = (const float*)d_in[2];
    const float* bq = (const float*)d_in[3];
    const float* Wk = (const float*)d_in[4];
    const float* bk = (const float*)d_in[5];
    float* out = (float*)d_out;

    cudaFuncSetAttribute(hedgehog_prep3, cudaFuncAttributeMaxDynamicSharedMemorySize, PREP_SMEM);
    cudaFuncSetAttribute(hedgehog_map1, cudaFuncAttributeMaxDynamicSharedMemorySize, M1_SMEM);
    cudaFuncSetAttribute(hedgehog_map2, cudaFuncAttributeMaxDynamicSharedMemorySize, M2_SMEM);
    hedgehog_prep3<<<1024, 256, PREP_SMEM>>>(q, k, Wq, bq, Wk, bk);
    hedgehog_ksum<<<64, 256>>>();
    hedgehog_map1<<<dim3(16, 64), 256, M1_SMEM>>>(out);
    hedgehog_map2<<<dim3(16, 64), 256, M2_SMEM>>>(out);
}